// round 7
// baseline (speedup 1.0000x reference)
#include <cuda_runtime.h>
#include <cuda_fp16.h>
#include <mma.h>
#include <math.h>
#include <stdint.h>

using namespace nvcuda;

#define Nn  20000
#define Ee  80000
#define Hh  64
#define NFf 32
#define Bb  64
#define HID 128

// ---------------- device scratch (no allocations allowed) ----------------
__device__ float  g_X[Nn * Hh];
__device__ float  g_agg[Nn * Hh];              // zeroed at load; k_gru re-zeroes after use
__device__ __half g_hid[Ee * HID];             // edge MLP hidden (fp16)
__device__ __half g_w2h[HID * Hh * Hh];        // W2 in fp16 (1 MB)
__device__ __half g_we[(size_t)Ee * Hh * Hh];  // 655 MB edge weights (fp16)
__device__ float  g_deg[Nn];
__device__ int    g_cnt[Bb];
__device__ int    g_ptr[Bb + 1];
__device__ float  g_en[Nn];
__device__ float  g_hs[Bb * Hh];
__device__ float  g_cs[Bb * Hh];
__device__ float  g_qstar[Bb * 2 * Hh];

__device__ __forceinline__ float sigf(float x) { return 1.0f / (1.0f + expf(-x)); }

// ---------------- prep: W2 -> fp16 ----------------
__global__ void k_prep(const float* __restrict__ w2) {
    int i4 = (blockIdx.x * 256 + threadIdx.x) * 4;
    float4 v = *(const float4*)&w2[i4];
    *(__half2*)&g_w2h[i4]     = __floats2half2_rn(v.x, v.y);
    *(__half2*)&g_w2h[i4 + 2] = __floats2half2_rn(v.z, v.w);
}

// ---------------- lin0: X = relu(x @ W0 + b0) ----------------
__global__ void k_lin0(const float* __restrict__ x, const float* __restrict__ w,
                       const float* __restrict__ b) {
    __shared__ float xs[NFf];
    int n = blockIdx.x, o = threadIdx.x;           // 64 threads
    if (o < NFf) xs[o] = x[n * NFf + o];
    __syncthreads();
    float acc = b[o];
#pragma unroll
    for (int i = 0; i < NFf; i++) acc = fmaf(xs[i], w[i * Hh + o], acc);
    g_X[n * Hh + o] = fmaxf(acc, 0.0f);
}

// ---------------- edge MLP layer 1: hid = fp16(relu(edge_attr @ W1 + b1)) ----------------
__global__ void k_mlp1(const float* __restrict__ ea, const float* __restrict__ w,
                       const float* __restrict__ b) {
    __shared__ float es[Hh];
    int e = blockIdx.x, j = threadIdx.x;           // 128 threads
    if (j < Hh) es[j] = ea[e * Hh + j];
    __syncthreads();
    float acc = b[j];
#pragma unroll
    for (int i = 0; i < Hh; i++) acc = fmaf(es[i], w[i * HID + j], acc);
    g_hid[e * HID + j] = __float2half_rn(fmaxf(acc, 0.0f));
}

// ---------------- big GEMM (fp16 HMMA) + fused iteration-1 msg ----------------
// Block: 64 edges, loops over all 64 N-tiles. A in smem once.
// Epilogue per tile: store we (fp16) + accumulate msg1 locally; atomics once at end.
#define ASTRD 136   // half stride (A: 64 x 128)
#define BSTRD 72    // half stride (B: 128 x 64)
#define CSTRD 68    // float stride (C stage / msg)
#define OFF_B   17408
#define OFF_C   35840
#define OFF_M   53248
#define OFF_X   70656
#define OFF_D   87040
#define GSM_TOTAL 87296

__global__ __launch_bounds__(256)
void k_gemm_we(const float* __restrict__ bias, const int* __restrict__ src,
               const int* __restrict__ dst) {
    extern __shared__ __align__(16) char sm[];
    __half* As  = (__half*)sm;               // 64 x 136
    __half* Bs  = (__half*)(sm + OFF_B);     // 128 x 72
    float*  Cs  = (float*)(sm + OFF_C);      // 64 x 68
    float*  Ms  = (float*)(sm + OFF_M);      // 64 x 68 (msg accumulator)
    float*  X1s = (float*)(sm + OFF_X);      // 64 x 64
    int*    Ds  = (int*)(sm + OFF_D);        // 64

    int t = threadIdx.x;            // 256
    int wid = t >> 5;
    int wr = wid & 3, wc = wid >> 2;
    int bm = blockIdx.x, e0 = bm * 64;

    // load A tile (64 x 128 half), X1 rows, dst ids, zero Ms
#pragma unroll
    for (int p = 0; p < 4; p++) {
        int idx = p * 256 + t;
        int r = idx >> 4, c = (idx & 15) * 8;
        *(uint4*)&As[r * ASTRD + c] = *(const uint4*)&g_hid[(size_t)(e0 + r) * HID + c];
    }
#pragma unroll
    for (int p = 0; p < 4; p++) {
        int idx = p * 256 + t;                  // 1024 float4 units
        int r = idx >> 4, c = (idx & 15) * 4;
        int sn = src[e0 + r];
        *(float4*)&X1s[r * 64 + c] = *(const float4*)&g_X[sn * Hh + c];
    }
    if (t < 64) Ds[t] = dst[e0 + t];
#pragma unroll
    for (int p = 0; p < 17; p++) {
        int idx = p * 256 + t;
        if (idx < 64 * CSTRD) Ms[idx] = 0.0f;
    }

    for (int bn = 0; bn < 64; bn++) {
        __syncthreads();   // Bs free (prev MMA done), Cs free (prev epilogue done)
        // load B tile: 128 rows x 64 halves
#pragma unroll
        for (int p = 0; p < 4; p++) {
            int idx = p * 256 + t;
            int r = idx >> 3, c = (idx & 7) * 8;
            *(uint4*)&Bs[r * BSTRD + c] = *(const uint4*)&g_w2h[(size_t)r * (Hh * Hh) + bn * 64 + c];
        }
        __syncthreads();

        wmma::fragment<wmma::accumulator, 16, 16, 16, float> c0, c1;
        wmma::fill_fragment(c0, 0.0f);
        wmma::fill_fragment(c1, 0.0f);
#pragma unroll
        for (int k16 = 0; k16 < 8; k16++) {
            wmma::fragment<wmma::matrix_a, 16, 16, 16, __half, wmma::row_major> af;
            wmma::fragment<wmma::matrix_b, 16, 16, 16, __half, wmma::row_major> bf0, bf1;
            wmma::load_matrix_sync(af, &As[(wr * 16) * ASTRD + k16 * 16], ASTRD);
            wmma::load_matrix_sync(bf0, &Bs[(k16 * 16) * BSTRD + wc * 32], BSTRD);
            wmma::load_matrix_sync(bf1, &Bs[(k16 * 16) * BSTRD + wc * 32 + 16], BSTRD);
            wmma::mma_sync(c0, af, bf0, c0);
            wmma::mma_sync(c1, af, bf1, c1);
        }
        wmma::store_matrix_sync(&Cs[(wr * 16) * CSTRD + wc * 32], c0, CSTRD, wmma::mem_row_major);
        wmma::store_matrix_sync(&Cs[(wr * 16) * CSTRD + wc * 32 + 16], c1, CSTRD, wmma::mem_row_major);
        __syncthreads();

        // epilogue: +bias -> fp16 store to g_we, msg1 accumulate into Ms
        __half* Cb = g_we + (size_t)e0 * (Hh * Hh) + bn * 64;
#pragma unroll
        for (int p = 0; p < 4; p++) {
            int idx = p * 256 + t;              // 1024 quads of 4 cols
            int r = idx >> 4, c = (idx & 15) * 4;
            float2 v0 = *(float2*)&Cs[r * CSTRD + c];
            float2 v1 = *(float2*)&Cs[r * CSTRD + c + 2];
            int cg = bn * 64 + c;
            v0.x += __ldg(&bias[cg]);     v0.y += __ldg(&bias[cg + 1]);
            v1.x += __ldg(&bias[cg + 2]); v1.y += __ldg(&bias[cg + 3]);
            __half2 h0 = __floats2half2_rn(v0.x, v0.y);
            __half2 h1 = __floats2half2_rn(v1.x, v1.y);
            uint2 pk = make_uint2(*(unsigned*)&h0, *(unsigned*)&h1);
            *(uint2*)&Cb[(size_t)r * (Hh * Hh) + c] = pk;
            float xv = X1s[r * 64 + bn];
            float* mp = &Ms[r * CSTRD + c];
            mp[0] = fmaf(xv, v0.x, mp[0]);
            mp[1] = fmaf(xv, v0.y, mp[1]);
            mp[2] = fmaf(xv, v1.x, mp[2]);
            mp[3] = fmaf(xv, v1.y, mp[3]);
        }
    }
    __syncthreads();
    // scatter msg1: 64 edges x 64 cols, 16 atomics per thread
#pragma unroll
    for (int p = 0; p < 16; p++) {
        int idx = p * 256 + t;
        int r = idx >> 6, c = idx & 63;
        atomicAdd(&g_agg[Ds[r] * Hh + c], Ms[r * CSTRD + c]);
    }
}

// ---------------- degree / batch counts ----------------
__global__ void k_deg(const int* __restrict__ dst) {
    int e = blockIdx.x * blockDim.x + threadIdx.x;
    if (e < Ee) atomicAdd(&g_deg[dst[e]], 1.0f);
}
__global__ void k_cnt(const int* __restrict__ batch) {
    int n = blockIdx.x * blockDim.x + threadIdx.x;
    if (n < Nn) atomicAdd(&g_cnt[batch[n]], 1);
}
__global__ void k_scan() {
    int t = threadIdx.x;           // 256 threads
    if (t == 0) {
        g_ptr[0] = 0;
        for (int b = 0; b < Bb; b++) g_ptr[b + 1] = g_ptr[b] + g_cnt[b];
    }
    for (int i = t; i < Bb * Hh; i += 256) { g_hs[i] = 0.0f; g_cs[i] = 0.0f; }
    for (int i = t; i < Bb * 2 * Hh; i += 256) g_qstar[i] = 0.0f;
}

// ---------------- per-edge matvec + scatter (iterations 2,3) ----------------
__global__ __launch_bounds__(256)
void k_msg(const int* __restrict__ src, const int* __restrict__ dst) {
    __shared__ float xs[4][Hh];
    __shared__ float red[4][8][Hh];
    int t = threadIdx.x;                    // 256
    int le = t >> 6;                        // local edge 0..3
    int u  = t & 63;                        // lane within edge
    int e  = blockIdx.x * 4 + le;
    int s = src[e], d = dst[e];
    xs[le][u] = g_X[s * Hh + u];
    __syncthreads();
    const __half* we = g_we + (size_t)e * Hh * Hh;
    int g = u >> 3, c8 = (u & 7) * 8;
    float acc[8] = {};
#pragma unroll
    for (int i = 0; i < 8; i++) {
        int ii = i * 8 + g;
        float xv = xs[le][ii];
        uint4 raw = __ldcs((const uint4*)&we[ii * Hh + c8]);
        const __half2* hp = (const __half2*)&raw;
#pragma unroll
        for (int j = 0; j < 4; j++) {
            float2 f = __half22float2(hp[j]);
            acc[2 * j]     = fmaf(xv, f.x, acc[2 * j]);
            acc[2 * j + 1] = fmaf(xv, f.y, acc[2 * j + 1]);
        }
    }
    *(float4*)&red[le][g][c8]     = make_float4(acc[0], acc[1], acc[2], acc[3]);
    *(float4*)&red[le][g][c8 + 4] = make_float4(acc[4], acc[5], acc[6], acc[7]);
    __syncthreads();
    float v = 0.0f;
#pragma unroll
    for (int g2 = 0; g2 < 8; g2++) v += red[le][g2][u];
    atomicAdd(&g_agg[d * Hh + u], v);
}

// ---------------- fused m = relu(agg/deg + X@root + cb) ; X = GRU(m, X) ----------------
__global__ void k_gru(const float* __restrict__ cr, const float* __restrict__ cb,
                      const float* __restrict__ wih, const float* __restrict__ whh,
                      const float* __restrict__ bih, const float* __restrict__ bhh) {
    __shared__ float xs[Hh], ms[Hh], gi[3 * Hh], gh[3 * Hh];
    int n = blockIdx.x, t = threadIdx.x;           // 192 threads
    if (t < Hh) xs[t] = g_X[n * Hh + t];
    __syncthreads();
    if (t < Hh) {
        float d = fmaxf(g_deg[n], 1.0f);
        float acc = g_agg[n * Hh + t] / d + cb[t];
        g_agg[n * Hh + t] = 0.0f;
#pragma unroll
        for (int i = 0; i < Hh; i++) acc = fmaf(xs[i], cr[i * Hh + t], acc);
        ms[t] = fmaxf(acc, 0.0f);
    }
    __syncthreads();
    {
        float a = bih[t], c = bhh[t];
#pragma unroll
        for (int i = 0; i < Hh; i++) {
            a = fmaf(ms[i], wih[i * 3 * Hh + t], a);
            c = fmaf(xs[i], whh[i * 3 * Hh + t], c);
        }
        gi[t] = a; gh[t] = c;
    }
    __syncthreads();
    if (t < Hh) {
        float r = sigf(gi[t] + gh[t]);
        float z = sigf(gi[Hh + t] + gh[Hh + t]);
        float ng = tanhf(gi[2 * Hh + t] + r * gh[2 * Hh + t]);
        g_X[n * Hh + t] = (1.0f - z) * ng + z * xs[t];
    }
}

// ---------------- Set2Set LSTM step ----------------
__global__ void k_lstm(const float* __restrict__ wih, const float* __restrict__ whh,
                       const float* __restrict__ bih, const float* __restrict__ bhh) {
    __shared__ float qs[2 * Hh], hr[Hh], g[4 * Hh];
    int b = blockIdx.x, t = threadIdx.x;           // 256 threads
    if (t < 2 * Hh) qs[t] = g_qstar[b * 2 * Hh + t];
    if (t < Hh) hr[t] = g_hs[b * Hh + t];
    __syncthreads();
    {
        float a = bih[t] + bhh[t];
#pragma unroll
        for (int i = 0; i < 2 * Hh; i++) a = fmaf(qs[i], wih[i * 4 * Hh + t], a);
#pragma unroll
        for (int i = 0; i < Hh; i++) a = fmaf(hr[i], whh[i * 4 * Hh + t], a);
        g[t] = a;
    }
    __syncthreads();
    if (t < Hh) {
        float ii = sigf(g[t]);
        float ff = sigf(g[Hh + t]);
        float gg = tanhf(g[2 * Hh + t]);
        float oo = sigf(g[3 * Hh + t]);
        float c2 = ff * g_cs[b * Hh + t] + ii * gg;
        float h2 = oo * tanhf(c2);
        g_cs[b * Hh + t] = c2;
        g_hs[b * Hh + t] = h2;
        g_qstar[b * 2 * Hh + t] = h2;
    }
}

// ---------------- en[n] = dot(X[n], hs[batch[n]]) ----------------
__global__ void k_en(const int* __restrict__ batch) {
    __shared__ float red[2];
    int n = blockIdx.x, o = threadIdx.x;           // 64 threads
    int b = batch[n];
    float v = g_X[n * Hh + o] * g_hs[b * Hh + o];
#pragma unroll
    for (int s = 16; s > 0; s >>= 1) v += __shfl_down_sync(0xffffffffu, v, s);
    if ((o & 31) == 0) red[o >> 5] = v;
    __syncthreads();
    if (o == 0) g_en[n] = red[0] + red[1];
}

// ---------------- per-graph softmax + weighted readout (4-way parallel pass 3) ----------------
__global__ __launch_bounds__(256)
void k_pool() {
    __shared__ float red[256];
    __shared__ float part[4][Hh];
    int b = blockIdx.x, t = threadIdx.x;           // 256 threads
    int s = g_ptr[b], e = g_ptr[b + 1];
    float m = -1e30f;
    for (int n = s + t; n < e; n += 256) m = fmaxf(m, g_en[n]);
    red[t] = m; __syncthreads();
    for (int st = 128; st > 0; st >>= 1) { if (t < st) red[t] = fmaxf(red[t], red[t + st]); __syncthreads(); }
    float mx = red[0]; __syncthreads();
    float ss = 0.0f;
    for (int n = s + t; n < e; n += 256) ss += expf(g_en[n] - mx);
    red[t] = ss; __syncthreads();
    for (int st = 128; st > 0; st >>= 1) { if (t < st) red[t] += red[t + st]; __syncthreads(); }
    float inv = 1.0f / (red[0] + 1e-16f);
    int ch = t >> 6, col = t & 63;
    float acc = 0.0f;
    for (int n = s + ch; n < e; n += 4) {
        float a = expf(g_en[n] - mx) * inv;
        acc = fmaf(a, g_X[n * Hh + col], acc);
    }
    part[ch][col] = acc; __syncthreads();
    if (t < Hh)
        g_qstar[b * 2 * Hh + Hh + t] = part[0][t] + part[1][t] + part[2][t] + part[3][t];
}

// ---------------- head ----------------
__global__ void k_final(const float* __restrict__ w1, const float* __restrict__ b1,
                        const float* __restrict__ w2, const float* __restrict__ b2,
                        float* __restrict__ out) {
    __shared__ float qs[2 * Hh], red[Hh];
    int b = blockIdx.x, t = threadIdx.x;           // 64 threads
    qs[t] = g_qstar[b * 2 * Hh + t];
    qs[Hh + t] = g_qstar[b * 2 * Hh + Hh + t];
    __syncthreads();
    float a = b1[t];
#pragma unroll
    for (int i = 0; i < 2 * Hh; i++) a = fmaf(qs[i], w1[i * Hh + t], a);
    a = fmaxf(a, 0.0f);
    red[t] = a * w2[t];
    __syncthreads();
    for (int st = 32; st > 0; st >>= 1) { if (t < st) red[t] += red[t + st]; __syncthreads(); }
    if (t == 0) out[b] = red[0] + b2[0];
}

// ---------------- launcher ----------------
extern "C" void kernel_launch(void* const* d_in, const int* in_sizes, int n_in,
                              void* d_out, int out_size) {
    const float* x         = (const float*)d_in[0];
    const int*   ei        = (const int*)d_in[1];
    const int*   batch     = (const int*)d_in[2];
    const float* edge_attr = (const float*)d_in[3];
    const float* lin0_w = (const float*)d_in[4];
    const float* lin0_b = (const float*)d_in[5];
    const float* nn_w1  = (const float*)d_in[6];
    const float* nn_b1  = (const float*)d_in[7];
    const float* nn_w2  = (const float*)d_in[8];
    const float* nn_b2  = (const float*)d_in[9];
    const float* conv_root = (const float*)d_in[10];
    const float* conv_bias = (const float*)d_in[11];
    const float* gru_wih = (const float*)d_in[12];
    const float* gru_whh = (const float*)d_in[13];
    const float* gru_bih = (const float*)d_in[14];
    const float* gru_bhh = (const float*)d_in[15];
    const float* lstm_wih = (const float*)d_in[16];
    const float* lstm_whh = (const float*)d_in[17];
    const float* lstm_bih = (const float*)d_in[18];
    const float* lstm_bhh = (const float*)d_in[19];
    const float* lin1_w = (const float*)d_in[20];
    const float* lin1_b = (const float*)d_in[21];
    const float* lin2_w = (const float*)d_in[22];
    const float* lin2_b = (const float*)d_in[23];

    const int* src = ei;
    const int* dst = ei + Ee;

    void *p_deg, *p_cnt;
    cudaGetSymbolAddress(&p_deg, g_deg);
    cudaGetSymbolAddress(&p_cnt, g_cnt);
    cudaMemsetAsync(p_deg, 0, Nn * sizeof(float), 0);
    cudaMemsetAsync(p_cnt, 0, Bb * sizeof(int), 0);

    static bool attr_done = false;
    if (!attr_done) {
        cudaFuncSetAttribute(k_gemm_we, cudaFuncAttributeMaxDynamicSharedMemorySize, GSM_TOTAL);
        attr_done = true;
    }

    // launch #4 (k_gemm_we) is the ncu-profiled one
    k_prep<<<512, 256>>>(nn_w2);                                     // 1
    k_lin0<<<Nn, Hh>>>(x, lin0_w, lin0_b);                           // 2
    k_mlp1<<<Ee, HID>>>(edge_attr, nn_w1, nn_b1);                    // 3
    k_gemm_we<<<Ee / 64, 256, GSM_TOTAL>>>(nn_b2, src, dst);         // 4 <- profiled (+ fused msg1)
    k_deg<<<(Ee + 255) / 256, 256>>>(dst);                           // 5
    k_cnt<<<(Nn + 255) / 256, 256>>>(batch);                         // 6
    k_scan<<<1, 256>>>();                                            // 7

    for (int it = 0; it < 3; it++) {
        if (it > 0) k_msg<<<Ee / 4, 256>>>(src, dst);
        k_gru<<<Nn, 3 * Hh>>>(conv_root, conv_bias, gru_wih, gru_whh, gru_bih, gru_bhh);
    }

    for (int st = 0; st < 3; st++) {
        k_lstm<<<Bb, 4 * Hh>>>(lstm_wih, lstm_whh, lstm_bih, lstm_bhh);
        k_en<<<Nn, Hh>>>(batch);
        k_pool<<<Bb, 256>>>();
    }

    k_final<<<Bb, Hh>>>(lin1_w, lin1_b, lin2_w, lin2_b, (float*)d_out);
}

// round 8
// speedup vs baseline: 1.0452x; 1.0452x over previous
#include <cuda_runtime.h>
#include <cuda_fp16.h>
#include <mma.h>
#include <math.h>
#include <stdint.h>

using namespace nvcuda;

#define Nn  20000
#define Ee  80000
#define Hh  64
#define NFf 32
#define Bb  64
#define HID 128

// ---------------- device scratch (no allocations allowed) ----------------
__device__ float  g_X[Nn * Hh];
__device__ float  g_agg[Nn * Hh];              // zeroed at load; k_gru re-zeroes after use
__device__ __half g_hid[Ee * HID];             // edge MLP hidden (fp16)
__device__ __half g_w2h[HID * Hh * Hh];        // W2 in fp16 (1 MB)
__device__ __half g_we[(size_t)Ee * Hh * Hh];  // 655 MB edge weights (fp16)
__device__ float  g_deg[Nn];
__device__ int    g_cnt[Bb];
__device__ int    g_ptr[Bb + 1];
__device__ float  g_en[Nn];
__device__ float  g_hs[Bb * Hh];
__device__ float  g_cs[Bb * Hh];
__device__ float  g_qstar[Bb * 2 * Hh];

__device__ __forceinline__ float sigf(float x) { return 1.0f / (1.0f + expf(-x)); }

// ---------------- prep: W2 -> fp16 ----------------
__global__ void k_prep(const float* __restrict__ w2) {
    int i4 = (blockIdx.x * 256 + threadIdx.x) * 4;
    float4 v = *(const float4*)&w2[i4];
    *(__half2*)&g_w2h[i4]     = __floats2half2_rn(v.x, v.y);
    *(__half2*)&g_w2h[i4 + 2] = __floats2half2_rn(v.z, v.w);
}

// ---------------- lin0: X = relu(x @ W0 + b0) ----------------
__global__ void k_lin0(const float* __restrict__ x, const float* __restrict__ w,
                       const float* __restrict__ b) {
    __shared__ float xs[NFf];
    int n = blockIdx.x, o = threadIdx.x;           // 64 threads
    if (o < NFf) xs[o] = x[n * NFf + o];
    __syncthreads();
    float acc = b[o];
#pragma unroll
    for (int i = 0; i < NFf; i++) acc = fmaf(xs[i], w[i * Hh + o], acc);
    g_X[n * Hh + o] = fmaxf(acc, 0.0f);
}

// ---------------- edge MLP layer 1: hid = fp16(relu(edge_attr @ W1 + b1)) ----------------
__global__ void k_mlp1(const float* __restrict__ ea, const float* __restrict__ w,
                       const float* __restrict__ b) {
    __shared__ float es[Hh];
    int e = blockIdx.x, j = threadIdx.x;           // 128 threads
    if (j < Hh) es[j] = ea[e * Hh + j];
    __syncthreads();
    float acc = b[j];
#pragma unroll
    for (int i = 0; i < Hh; i++) acc = fmaf(es[i], w[i * HID + j], acc);
    g_hid[e * HID + j] = __float2half_rn(fmaxf(acc, 0.0f));
}

// ---------------- big GEMM (fp16 HMMA, round-4 config): we = fp16(hid @ W2 + b2) ----------------
#define GBM 64
#define GBN 64
#define GBK 64
#define HSTR 72
#define BSTRc 68
__global__ __launch_bounds__(256)
void k_gemm_we(const float* __restrict__ bias) {
    __shared__ __half As[GBM * HSTR];     // 64 x 72 half
    __shared__ __half Bs[GBK * HSTR];     // 64 x 72 half
    __shared__ float  Cs[GBM * BSTRc];    // 64 x 68 float (epilogue)

    int bn = blockIdx.x;            // 0..63  (col tile)
    int bm = blockIdx.y;            // 0..1249 (row tile)
    int t  = threadIdx.x;           // 256
    int wid = t >> 5;
    int rt = wid & 3;               // 16-row tile
    int ct = wid >> 2;              // 32-col half

    wmma::fragment<wmma::accumulator, 16, 16, 16, float> c0, c1;
    wmma::fill_fragment(c0, 0.0f);
    wmma::fill_fragment(c1, 0.0f);

    const __half* A = g_hid + (size_t)bm * GBM * HID;
    const __half* Bg = g_w2h + bn * GBN;

    int lr = t >> 3;                // 0..31
    int lc = (t & 7) * 8;           // half-index, 8 halfs = 16B

    for (int kt = 0; kt < HID; kt += GBK) {
        *(float4*)&As[lr * HSTR + lc]        = *(const float4*)&A[lr * HID + kt + lc];
        *(float4*)&As[(lr + 32) * HSTR + lc] = *(const float4*)&A[(lr + 32) * HID + kt + lc];
        *(float4*)&Bs[lr * HSTR + lc]        = *(const float4*)&Bg[(size_t)(kt + lr) * (Hh * Hh) + lc];
        *(float4*)&Bs[(lr + 32) * HSTR + lc] = *(const float4*)&Bg[(size_t)(kt + lr + 32) * (Hh * Hh) + lc];
        __syncthreads();
#pragma unroll
        for (int k16 = 0; k16 < GBK / 16; k16++) {
            wmma::fragment<wmma::matrix_a, 16, 16, 16, __half, wmma::row_major> af;
            wmma::fragment<wmma::matrix_b, 16, 16, 16, __half, wmma::row_major> bf0, bf1;
            wmma::load_matrix_sync(af, &As[rt * 16 * HSTR + k16 * 16], HSTR);
            wmma::load_matrix_sync(bf0, &Bs[k16 * 16 * HSTR + ct * 32], HSTR);
            wmma::load_matrix_sync(bf1, &Bs[k16 * 16 * HSTR + ct * 32 + 16], HSTR);
            wmma::mma_sync(c0, af, bf0, c0);
            wmma::mma_sync(c1, af, bf1, c1);
        }
        __syncthreads();
    }

    wmma::store_matrix_sync(&Cs[rt * 16 * BSTRc + ct * 32], c0, BSTRc, wmma::mem_row_major);
    wmma::store_matrix_sync(&Cs[rt * 16 * BSTRc + ct * 32 + 16], c1, BSTRc, wmma::mem_row_major);
    __syncthreads();

    __half* C = g_we + (size_t)bm * GBM * (Hh * Hh) + bn * GBN;
#pragma unroll
    for (int p = 0; p < 4; p++) {
        int idx = p * 1024 + t * 4;
        int r = idx >> 6, c = idx & 63;
        float4 v = *(float4*)&Cs[r * BSTRc + c];
        int cg = bn * GBN + c;
        v.x += bias[cg + 0]; v.y += bias[cg + 1];
        v.z += bias[cg + 2]; v.w += bias[cg + 3];
        __half2 h0 = __floats2half2_rn(v.x, v.y);
        __half2 h1 = __floats2half2_rn(v.z, v.w);
        *(__half2*)&C[(size_t)r * (Hh * Hh) + c] = h0;
        *(__half2*)&C[(size_t)r * (Hh * Hh) + c + 2] = h1;
    }
}

// ---------------- degree / batch counts ----------------
__global__ void k_deg(const int* __restrict__ dst) {
    int e = blockIdx.x * blockDim.x + threadIdx.x;
    if (e < Ee) atomicAdd(&g_deg[dst[e]], 1.0f);
}
__global__ void k_cnt(const int* __restrict__ batch) {
    int n = blockIdx.x * blockDim.x + threadIdx.x;
    if (n < Nn) atomicAdd(&g_cnt[batch[n]], 1);
}
__global__ void k_scan() {
    int t = threadIdx.x;           // 256 threads
    if (t == 0) {
        g_ptr[0] = 0;
        for (int b = 0; b < Bb; b++) g_ptr[b + 1] = g_ptr[b] + g_cnt[b];
    }
    for (int i = t; i < Bb * Hh; i += 256) { g_hs[i] = 0.0f; g_cs[i] = 0.0f; }
    for (int i = t; i < Bb * 2 * Hh; i += 256) g_qstar[i] = 0.0f;
}

// ---------------- per-edge matvec + scatter: 8 threads/edge, register-only accumulation ----
// 256 threads = 32 edges/block. Thread owns 8 output cols; loops all 64 i.
__global__ __launch_bounds__(256)
void k_msg(const int* __restrict__ src, const int* __restrict__ dst) {
    __shared__ float xs[32][Hh];
    __shared__ int   sid[32], did[32];
    int t = threadIdx.x;                    // 256
    int e0 = blockIdx.x * 32;
    if (t < 32) { sid[t] = src[e0 + t]; did[t] = dst[e0 + t]; }
    __syncthreads();
    // load X rows for 32 edges: 2048 floats, 8 per thread
#pragma unroll
    for (int p = 0; p < 8; p++) {
        int idx = p * 256 + t;
        int le2 = idx >> 6, c = idx & 63;
        xs[le2][c] = g_X[sid[le2] * Hh + c];
    }
    __syncthreads();

    int le = t >> 3;                        // edge 0..31
    int c8 = (t & 7) * 8;                   // 8 cols
    const __half* we = g_we + (size_t)(e0 + le) * Hh * Hh + c8;
    float acc[8] = {};
#pragma unroll 8
    for (int i = 0; i < Hh; i++) {
        float xv = xs[le][i];
        uint4 raw = __ldcs((const uint4*)(we + i * Hh));
        const __half2* hp = (const __half2*)&raw;
#pragma unroll
        for (int j = 0; j < 4; j++) {
            float2 f = __half22float2(hp[j]);
            acc[2 * j]     = fmaf(xv, f.x, acc[2 * j]);
            acc[2 * j + 1] = fmaf(xv, f.y, acc[2 * j + 1]);
        }
    }
    float* ap = &g_agg[did[le] * Hh + c8];
#pragma unroll
    for (int j = 0; j < 8; j++) atomicAdd(&ap[j], acc[j]);
}

// ---------------- fused m = relu(agg/deg + X@root + cb) ; X = GRU(m, X) ----------------
__global__ void k_gru(const float* __restrict__ cr, const float* __restrict__ cb,
                      const float* __restrict__ wih, const float* __restrict__ whh,
                      const float* __restrict__ bih, const float* __restrict__ bhh) {
    __shared__ float xs[Hh], ms[Hh], gi[3 * Hh], gh[3 * Hh];
    int n = blockIdx.x, t = threadIdx.x;           // 192 threads
    if (t < Hh) xs[t] = g_X[n * Hh + t];
    __syncthreads();
    if (t < Hh) {
        float d = fmaxf(g_deg[n], 1.0f);
        float acc = g_agg[n * Hh + t] / d + cb[t];
        g_agg[n * Hh + t] = 0.0f;
#pragma unroll
        for (int i = 0; i < Hh; i++) acc = fmaf(xs[i], cr[i * Hh + t], acc);
        ms[t] = fmaxf(acc, 0.0f);
    }
    __syncthreads();
    {
        float a = bih[t], c = bhh[t];
#pragma unroll
        for (int i = 0; i < Hh; i++) {
            a = fmaf(ms[i], wih[i * 3 * Hh + t], a);
            c = fmaf(xs[i], whh[i * 3 * Hh + t], c);
        }
        gi[t] = a; gh[t] = c;
    }
    __syncthreads();
    if (t < Hh) {
        float r = sigf(gi[t] + gh[t]);
        float z = sigf(gi[Hh + t] + gh[Hh + t]);
        float ng = tanhf(gi[2 * Hh + t] + r * gh[2 * Hh + t]);
        g_X[n * Hh + t] = (1.0f - z) * ng + z * xs[t];
    }
}

// ---------------- Set2Set LSTM step ----------------
__global__ void k_lstm(const float* __restrict__ wih, const float* __restrict__ whh,
                       const float* __restrict__ bih, const float* __restrict__ bhh) {
    __shared__ float qs[2 * Hh], hr[Hh], g[4 * Hh];
    int b = blockIdx.x, t = threadIdx.x;           // 256 threads
    if (t < 2 * Hh) qs[t] = g_qstar[b * 2 * Hh + t];
    if (t < Hh) hr[t] = g_hs[b * Hh + t];
    __syncthreads();
    {
        float a = bih[t] + bhh[t];
#pragma unroll
        for (int i = 0; i < 2 * Hh; i++) a = fmaf(qs[i], wih[i * 4 * Hh + t], a);
#pragma unroll
        for (int i = 0; i < Hh; i++) a = fmaf(hr[i], whh[i * 4 * Hh + t], a);
        g[t] = a;
    }
    __syncthreads();
    if (t < Hh) {
        float ii = sigf(g[t]);
        float ff = sigf(g[Hh + t]);
        float gg = tanhf(g[2 * Hh + t]);
        float oo = sigf(g[3 * Hh + t]);
        float c2 = ff * g_cs[b * Hh + t] + ii * gg;
        float h2 = oo * tanhf(c2);
        g_cs[b * Hh + t] = c2;
        g_hs[b * Hh + t] = h2;
        g_qstar[b * 2 * Hh + t] = h2;
    }
}

// ---------------- en[n] = dot(X[n], hs[batch[n]]) ----------------
__global__ void k_en(const int* __restrict__ batch) {
    __shared__ float red[2];
    int n = blockIdx.x, o = threadIdx.x;           // 64 threads
    int b = batch[n];
    float v = g_X[n * Hh + o] * g_hs[b * Hh + o];
#pragma unroll
    for (int s = 16; s > 0; s >>= 1) v += __shfl_down_sync(0xffffffffu, v, s);
    if ((o & 31) == 0) red[o >> 5] = v;
    __syncthreads();
    if (o == 0) g_en[n] = red[0] + red[1];
}

// ---------------- per-graph softmax + weighted readout (4-way parallel pass 3) ----------------
__global__ __launch_bounds__(256)
void k_pool() {
    __shared__ float red[256];
    __shared__ float part[4][Hh];
    int b = blockIdx.x, t = threadIdx.x;           // 256 threads
    int s = g_ptr[b], e = g_ptr[b + 1];
    float m = -1e30f;
    for (int n = s + t; n < e; n += 256) m = fmaxf(m, g_en[n]);
    red[t] = m; __syncthreads();
    for (int st = 128; st > 0; st >>= 1) { if (t < st) red[t] = fmaxf(red[t], red[t + st]); __syncthreads(); }
    float mx = red[0]; __syncthreads();
    float ss = 0.0f;
    for (int n = s + t; n < e; n += 256) ss += expf(g_en[n] - mx);
    red[t] = ss; __syncthreads();
    for (int st = 128; st > 0; st >>= 1) { if (t < st) red[t] += red[t + st]; __syncthreads(); }
    float inv = 1.0f / (red[0] + 1e-16f);
    int ch = t >> 6, col = t & 63;
    float acc = 0.0f;
    for (int n = s + ch; n < e; n += 4) {
        float a = expf(g_en[n] - mx) * inv;
        acc = fmaf(a, g_X[n * Hh + col], acc);
    }
    part[ch][col] = acc; __syncthreads();
    if (t < Hh)
        g_qstar[b * 2 * Hh + Hh + t] = part[0][t] + part[1][t] + part[2][t] + part[3][t];
}

// ---------------- head ----------------
__global__ void k_final(const float* __restrict__ w1, const float* __restrict__ b1,
                        const float* __restrict__ w2, const float* __restrict__ b2,
                        float* __restrict__ out) {
    __shared__ float qs[2 * Hh], red[Hh];
    int b = blockIdx.x, t = threadIdx.x;           // 64 threads
    qs[t] = g_qstar[b * 2 * Hh + t];
    qs[Hh + t] = g_qstar[b * 2 * Hh + Hh + t];
    __syncthreads();
    float a = b1[t];
#pragma unroll
    for (int i = 0; i < 2 * Hh; i++) a = fmaf(qs[i], w1[i * Hh + t], a);
    a = fmaxf(a, 0.0f);
    red[t] = a * w2[t];
    __syncthreads();
    for (int st = 32; st > 0; st >>= 1) { if (t < st) red[t] += red[t + st]; __syncthreads(); }
    if (t == 0) out[b] = red[0] + b2[0];
}

// ---------------- launcher ----------------
extern "C" void kernel_launch(void* const* d_in, const int* in_sizes, int n_in,
                              void* d_out, int out_size) {
    const float* x         = (const float*)d_in[0];
    const int*   ei        = (const int*)d_in[1];
    const int*   batch     = (const int*)d_in[2];
    const float* edge_attr = (const float*)d_in[3];
    const float* lin0_w = (const float*)d_in[4];
    const float* lin0_b = (const float*)d_in[5];
    const float* nn_w1  = (const float*)d_in[6];
    const float* nn_b1  = (const float*)d_in[7];
    const float* nn_w2  = (const float*)d_in[8];
    const float* nn_b2  = (const float*)d_in[9];
    const float* conv_root = (const float*)d_in[10];
    const float* conv_bias = (const float*)d_in[11];
    const float* gru_wih = (const float*)d_in[12];
    const float* gru_whh = (const float*)d_in[13];
    const float* gru_bih = (const float*)d_in[14];
    const float* gru_bhh = (const float*)d_in[15];
    const float* lstm_wih = (const float*)d_in[16];
    const float* lstm_whh = (const float*)d_in[17];
    const float* lstm_bih = (const float*)d_in[18];
    const float* lstm_bhh = (const float*)d_in[19];
    const float* lin1_w = (const float*)d_in[20];
    const float* lin1_b = (const float*)d_in[21];
    const float* lin2_w = (const float*)d_in[22];
    const float* lin2_b = (const float*)d_in[23];

    const int* src = ei;
    const int* dst = ei + Ee;

    void *p_deg, *p_cnt;
    cudaGetSymbolAddress(&p_deg, g_deg);
    cudaGetSymbolAddress(&p_cnt, g_cnt);
    cudaMemsetAsync(p_deg, 0, Nn * sizeof(float), 0);
    cudaMemsetAsync(p_cnt, 0, Bb * sizeof(int), 0);

    // launch #4 (k_gemm_we) is the ncu-profiled one
    k_prep<<<512, 256>>>(nn_w2);                                     // 1
    k_lin0<<<Nn, Hh>>>(x, lin0_w, lin0_b);                           // 2
    k_mlp1<<<Ee, HID>>>(edge_attr, nn_w1, nn_b1);                    // 3
    k_gemm_we<<<dim3((Hh * Hh) / GBN, Ee / GBM), 256>>>(nn_b2);      // 4 <- profiled
    k_deg<<<(Ee + 255) / 256, 256>>>(dst);                           // 5
    k_cnt<<<(Nn + 255) / 256, 256>>>(batch);                         // 6
    k_scan<<<1, 256>>>();                                            // 7

    for (int it = 0; it < 3; it++) {
        k_msg<<<Ee / 32, 256>>>(src, dst);
        k_gru<<<Nn, 3 * Hh>>>(conv_root, conv_bias, gru_wih, gru_whh, gru_bih, gru_bhh);
    }

    for (int st = 0; st < 3; st++) {
        k_lstm<<<Bb, 4 * Hh>>>(lstm_wih, lstm_whh, lstm_bih, lstm_bhh);
        k_en<<<Nn, Hh>>>(batch);
        k_pool<<<Bb, 256>>>();
    }

    k_final<<<Bb, Hh>>>(lin1_w, lin1_b, lin2_w, lin2_b, (float*)d_out);
}